// round 6
// baseline (speedup 1.0000x reference)
#include <cuda_runtime.h>
#include <cuda_fp16.h>
#include <cstdint>

#define NROWS 100000
#define D     128
#define PP    8192
#define NEG   256
#define TEMPF 0.07f

// Scratch (device globals: allocation-free per harness rules)
__device__ __align__(16) __half g_embh[ (size_t)NROWS * D ];   // fp16 projected embeddings
__device__ float g_losses[2 * PP];

union U64 { unsigned long long u; float2 f; };

__device__ __forceinline__ unsigned long long fma2(unsigned long long a,
                                                   unsigned long long b,
                                                   unsigned long long c) {
    unsigned long long d;
    asm("fma.rn.f32x2 %0, %1, %2, %3;" : "=l"(d) : "l"(a), "l"(b), "l"(c));
    return d;
}

// ---------------------------------------------------------------------------
// Kernel 1: embh = fp16(X @ W^T + b)
// 256 threads = 8 warps, 4 rows/warp -> 32 rows/CTA (grid 3125, exact).
// launch_bounds(256,3) caps regs so 3 CTAs/SM (24 warps) hide memory latency.
// W transposed in padded dynamic smem; X read as warp-broadcast float4 with
// one-chunk-ahead prefetch. FMA pipe (f32x2) is the binding resource.
// ---------------------------------------------------------------------------
#define GW 132
#define GEMM_SMEM (128 * GW * 4)   // 67584 B

__global__ void __launch_bounds__(256, 3) gemm_kernel(const float* __restrict__ X,
                                                      const float* __restrict__ W,
                                                      const float* __restrict__ b) {
    extern __shared__ float Wt[];   // Wt[k*GW + d] = W[d][k]

    int tid  = threadIdx.x;
    int lane = tid & 31;
    int warp = tid >> 5;

    // coalesced float4 read of W, transposed scalar stores (pad 132 -> 2-way)
    const float4* W4 = (const float4*)W;
    for (int i = tid; i < D * D / 4; i += 256) {
        int d  = i >> 5;
        int k0 = (i & 31) << 2;
        float4 w = W4[i];
        Wt[(k0 + 0) * GW + d] = w.x;
        Wt[(k0 + 1) * GW + d] = w.y;
        Wt[(k0 + 2) * GW + d] = w.z;
        Wt[(k0 + 3) * GW + d] = w.w;
    }
    __syncthreads();

    int d0   = lane * 4;
    int row0 = blockIdx.x * 32 + warp * 4;          // always < NROWS (3125*32 = 100000)
    const float* xb = X + (size_t)row0 * D;

    float4 bv = *(const float4*)(b + d0);
    U64 acc[4][2];
#pragma unroll
    for (int r = 0; r < 4; r++) {
        acc[r][0].f = make_float2(bv.x, bv.y);
        acc[r][1].f = make_float2(bv.z, bv.w);
    }

    float4 xr[4], xn[4];
#pragma unroll
    for (int r = 0; r < 4; r++) xr[r] = __ldg((const float4*)(xb + r * D));

#pragma unroll 2
    for (int kc = 0; kc < D; kc += 4) {
        int nxt = (kc + 4) & (D - 1);               // wraps on last iter (result unused)
#pragma unroll
        for (int r = 0; r < 4; r++)
            xn[r] = __ldg((const float4*)(xb + r * D + nxt));

#pragma unroll
        for (int kk = 0; kk < 4; kk++) {
            float4 wv = *(const float4*)(Wt + (kc + kk) * GW + d0);
            U64 w01, w23;
            w01.f = make_float2(wv.x, wv.y);
            w23.f = make_float2(wv.z, wv.w);
#pragma unroll
            for (int r = 0; r < 4; r++) {
                float xv = (kk == 0) ? xr[r].x : (kk == 1) ? xr[r].y
                         : (kk == 2) ? xr[r].z : xr[r].w;
                U64 xx; xx.f = make_float2(xv, xv);
                acc[r][0].u = fma2(xx.u, w01.u, acc[r][0].u);
                acc[r][1].u = fma2(xx.u, w23.u, acc[r][1].u);
            }
        }
#pragma unroll
        for (int r = 0; r < 4; r++) xr[r] = xn[r];
    }

#pragma unroll
    for (int r = 0; r < 4; r++) {
        size_t off = (size_t)(row0 + r) * D + d0;
        __half2 p0 = __floats2half2_rn(acc[r][0].f.x, acc[r][0].f.y);
        __half2 p1 = __floats2half2_rn(acc[r][1].f.x, acc[r][1].f.y);
        *(uint2*)(g_embh + off) = make_uint2(*(uint32_t*)&p0, *(uint32_t*)&p1);
    }
}

// ---------------------------------------------------------------------------
// Kernel 2: per (p, branch): logits, logsumexp, per-pair loss.
// q,k,negatives all from fp16 embeddings; fp32 dot accumulation.
// ---------------------------------------------------------------------------
__global__ void branch_kernel(const int* __restrict__ pos_anchor,
                              const int* __restrict__ pos_partner,
                              const int* __restrict__ neg_idx,
                              const int* __restrict__ weak_anchor,
                              const int* __restrict__ weak_partner,
                              const int* __restrict__ weak_neg_idx) {
    __shared__ float qsh[D], ksh[D];
    __shared__ int   sidx[NEG];
    __shared__ float sdots[NEG + 1];
    __shared__ float sred[9];

    int p  = blockIdx.x;
    int br = blockIdx.y;
    const int* anc = br ? weak_anchor  : pos_anchor;
    const int* par = br ? weak_partner : pos_partner;
    const int* nix = br ? weak_neg_idx : neg_idx;

    int tid  = threadIdx.x;
    int lane = tid & 31;
    int warp = tid >> 5;

    int a  = anc[p];
    int pr = par[p];
    if (tid < D) qsh[tid]     = __half2float(g_embh[(size_t)a  * D + tid]);
    else         ksh[tid - D] = __half2float(g_embh[(size_t)pr * D + (tid - D)]);
    sidx[tid] = nix[(size_t)p * NEG + tid];
    __syncthreads();

    int hl   = lane & 15;
    int half = lane >> 4;

    float qr[8];
#pragma unroll
    for (int j = 0; j < 8; j++) qr[j] = qsh[hl * 8 + j];

    // positive dot (warp 0)
    if (warp == 0) {
        float s = 0.f;
#pragma unroll
        for (int j = 0; j < 4; j++) s += qsh[lane * 4 + j] * ksh[lane * 4 + j];
#pragma unroll
        for (int m = 16; m >= 1; m >>= 1) s += __shfl_xor_sync(0xffffffffu, s, m);
        if (lane == 0) sdots[NEG] = s;
    }

    // negatives: 2 per warp-iteration, 16 lanes each (uint4 = 8 halves/lane)
#pragma unroll 4
    for (int it = 0; it < 16; it++) {
        int n   = warp * 32 + it * 2 + half;
        int rw  = sidx[n];
        uint4 v = *(const uint4*)(g_embh + (size_t)rw * D + hl * 8);
        __half2* h2 = (__half2*)&v;
        float s = 0.f;
#pragma unroll
        for (int j = 0; j < 4; j++) {
            float2 f = __half22float2(h2[j]);
            s = fmaf(qr[2 * j],     f.x, s);
            s = fmaf(qr[2 * j + 1], f.y, s);
        }
        s += __shfl_xor_sync(0xffffffffu, s, 8);
        s += __shfl_xor_sync(0xffffffffu, s, 4);
        s += __shfl_xor_sync(0xffffffffu, s, 2);
        s += __shfl_xor_sync(0xffffffffu, s, 1);
        if (hl == 0) sdots[n] = s;
    }
    __syncthreads();

    const float invT = 1.0f / TEMPF;

    float v = sdots[tid];
    float mv = (tid == 0) ? fmaxf(v, sdots[NEG]) : v;
#pragma unroll
    for (int m = 16; m >= 1; m >>= 1) mv = fmaxf(mv, __shfl_xor_sync(0xffffffffu, mv, m));
    if (lane == 0) sred[warp] = mv;
    __syncthreads();
    if (tid == 0) {
        float m2 = sred[0];
#pragma unroll
        for (int i = 1; i < 8; i++) m2 = fmaxf(m2, sred[i]);
        sred[8] = m2;
    }
    __syncthreads();
    float ml = sred[8] * invT;

    float e = expf(v * invT - ml);
    if (tid == 0) e += expf(sdots[NEG] * invT - ml);
#pragma unroll
    for (int m = 16; m >= 1; m >>= 1) e += __shfl_xor_sync(0xffffffffu, e, m);
    if (lane == 0) sred[warp] = e;
    __syncthreads();
    if (tid == 0) {
        float s = 0.f;
#pragma unroll
        for (int i = 0; i < 8; i++) s += sred[i];
        g_losses[br * PP + p] = ml + logf(s) - sdots[NEG] * invT;
    }
}

// ---------------------------------------------------------------------------
// Kernel 3: deterministic mean reduction, out = mean0 + 0.1 * mean1
// ---------------------------------------------------------------------------
__global__ void finalize_kernel(float* __restrict__ out) {
    __shared__ double s0sh[256], s1sh[256];
    int tid = threadIdx.x;
    double s0 = 0.0, s1 = 0.0;
    for (int i = tid; i < PP; i += 256) {
        s0 += (double)g_losses[i];
        s1 += (double)g_losses[PP + i];
    }
    s0sh[tid] = s0; s1sh[tid] = s1;
    __syncthreads();
    for (int st = 128; st > 0; st >>= 1) {
        if (tid < st) { s0sh[tid] += s0sh[tid + st]; s1sh[tid] += s1sh[tid + st]; }
        __syncthreads();
    }
    if (tid == 0)
        out[0] = (float)(s0sh[0] / (double)PP + 0.1 * (s1sh[0] / (double)PP));
}

extern "C" void kernel_launch(void* const* d_in, const int* in_sizes, int n_in,
                              void* d_out, int out_size) {
    const float* X  = (const float*)d_in[0];
    const float* W  = (const float*)d_in[1];
    const float* b  = (const float*)d_in[2];
    const int*   pa = (const int*)d_in[3];
    const int*   pp = (const int*)d_in[4];
    const int*   ni = (const int*)d_in[5];
    const int*   wa = (const int*)d_in[6];
    const int*   wp = (const int*)d_in[7];
    const int*   wn = (const int*)d_in[8];
    float* out = (float*)d_out;

    cudaFuncSetAttribute(gemm_kernel, cudaFuncAttributeMaxDynamicSharedMemorySize, GEMM_SMEM);

    gemm_kernel<<<NROWS / 32, 256, GEMM_SMEM>>>(X, W, b);   // 3125 blocks, exact
    branch_kernel<<<dim3(PP, 2), 256>>>(pa, pp, ni, wa, wp, wn);
    finalize_kernel<<<1, 256>>>(out);
}

// round 7
// speedup vs baseline: 1.2716x; 1.2716x over previous
#include <cuda_runtime.h>
#include <cuda_fp16.h>
#include <cstdint>

#define NROWS 100000
#define D     128
#define PP    8192
#define NEG   256
#define TEMPF 0.07f

// Scratch (device globals: allocation-free per harness rules)
__device__ __align__(16) __half g_embh[ (size_t)NROWS * D ];   // fp16 projected embeddings
__device__ float g_losses[2 * PP];

union U64 { unsigned long long u; float2 f; };

__device__ __forceinline__ unsigned long long fma2(unsigned long long a,
                                                   unsigned long long b,
                                                   unsigned long long c) {
    unsigned long long d;
    asm("fma.rn.f32x2 %0, %1, %2, %3;" : "=l"(d) : "l"(a), "l"(b), "l"(c));
    return d;
}

// ---------------------------------------------------------------------------
// Kernel 1: embh = fp16(X @ W^T + b)
// 256 threads = 8 warps, 8 rows/warp -> 64 rows/CTA, 2 CTAs/SM.
// W transposed in padded smem (LDS.128/lane); X tile staged in smem once via
// coalesced float4 loads, then read as broadcast LDS (1 wavefront).
// FMA (f32x2) pipe is the binding resource.
// ---------------------------------------------------------------------------
#define GW 132
#define RPW 8                                   // rows per warp
#define RPB 64                                  // rows per block
#define GEMM_SMEM ((128 * GW + RPB * D) * 4)    // 67584 + 32768 = 100352 B

__global__ void __launch_bounds__(256, 2) gemm_kernel(const float* __restrict__ X,
                                                      const float* __restrict__ W,
                                                      const float* __restrict__ b) {
    extern __shared__ float sh[];
    float* Wt = sh;              // Wt[k*GW + d] = W[d][k]
    float* Xs = sh + 128 * GW;   // Xs[r][k], 64x128

    int tid  = threadIdx.x;
    int lane = tid & 31;
    int warp = tid >> 5;

    // W: coalesced float4 read, transposed scalar stores (pad 132)
    const float4* W4 = (const float4*)W;
    for (int i = tid; i < D * D / 4; i += 256) {
        int d  = i >> 5;
        int k0 = (i & 31) << 2;
        float4 w = W4[i];
        Wt[(k0 + 0) * GW + d] = w.x;
        Wt[(k0 + 1) * GW + d] = w.y;
        Wt[(k0 + 2) * GW + d] = w.z;
        Wt[(k0 + 3) * GW + d] = w.w;
    }

    // X tile: coalesced float4 stage (clamp overflow rows; stores guarded later)
    int row0 = blockIdx.x * RPB;
    for (int i = tid; i < RPB * D / 4; i += 256) {
        int r = i >> 5, c = i & 31;
        int gr = row0 + r;
        if (gr >= NROWS) gr = NROWS - 1;
        ((float4*)Xs)[i] = __ldg((const float4*)(X + (size_t)gr * D) + c);
    }
    __syncthreads();

    int d0 = lane * 4;
    float4 bv = *(const float4*)(b + d0);

    U64 acc[RPW][2];
#pragma unroll
    for (int r = 0; r < RPW; r++) {
        acc[r][0].f = make_float2(bv.x, bv.y);
        acc[r][1].f = make_float2(bv.z, bv.w);
    }

    int rbase = warp * RPW;

#pragma unroll 2
    for (int kc = 0; kc < D; kc += 4) {
        float4 xv[RPW];
#pragma unroll
        for (int r = 0; r < RPW; r++)
            xv[r] = *(const float4*)(Xs + (rbase + r) * D + kc);   // broadcast LDS

#pragma unroll
        for (int kk = 0; kk < 4; kk++) {
            float4 wv = *(const float4*)(Wt + (kc + kk) * GW + d0);
            U64 w01, w23;
            w01.f = make_float2(wv.x, wv.y);
            w23.f = make_float2(wv.z, wv.w);
#pragma unroll
            for (int r = 0; r < RPW; r++) {
                float xvv = (kk == 0) ? xv[r].x : (kk == 1) ? xv[r].y
                          : (kk == 2) ? xv[r].z : xv[r].w;
                U64 xx; xx.f = make_float2(xvv, xvv);
                acc[r][0].u = fma2(xx.u, w01.u, acc[r][0].u);
                acc[r][1].u = fma2(xx.u, w23.u, acc[r][1].u);
            }
        }
    }

#pragma unroll
    for (int r = 0; r < RPW; r++) {
        int rw = row0 + rbase + r;
        if (rw < NROWS) {
            size_t off = (size_t)rw * D + d0;
            __half2 p0 = __floats2half2_rn(acc[r][0].f.x, acc[r][0].f.y);
            __half2 p1 = __floats2half2_rn(acc[r][1].f.x, acc[r][1].f.y);
            *(uint2*)(g_embh + off) = make_uint2(*(uint32_t*)&p0, *(uint32_t*)&p1);
        }
    }
}

// ---------------------------------------------------------------------------
// Kernel 2: per (p, branch): logits, logsumexp, per-pair loss.
// q,k,negatives all from fp16 embeddings; fp32 dot accumulation.
// ---------------------------------------------------------------------------
__global__ void branch_kernel(const int* __restrict__ pos_anchor,
                              const int* __restrict__ pos_partner,
                              const int* __restrict__ neg_idx,
                              const int* __restrict__ weak_anchor,
                              const int* __restrict__ weak_partner,
                              const int* __restrict__ weak_neg_idx) {
    __shared__ float qsh[D], ksh[D];
    __shared__ int   sidx[NEG];
    __shared__ float sdots[NEG + 1];
    __shared__ float sred[9];

    int p  = blockIdx.x;
    int br = blockIdx.y;
    const int* anc = br ? weak_anchor  : pos_anchor;
    const int* par = br ? weak_partner : pos_partner;
    const int* nix = br ? weak_neg_idx : neg_idx;

    int tid  = threadIdx.x;
    int lane = tid & 31;
    int warp = tid >> 5;

    int a  = anc[p];
    int pr = par[p];
    if (tid < D) qsh[tid]     = __half2float(g_embh[(size_t)a  * D + tid]);
    else         ksh[tid - D] = __half2float(g_embh[(size_t)pr * D + (tid - D)]);
    sidx[tid] = nix[(size_t)p * NEG + tid];
    __syncthreads();

    int hl   = lane & 15;
    int half = lane >> 4;

    float qr[8];
#pragma unroll
    for (int j = 0; j < 8; j++) qr[j] = qsh[hl * 8 + j];

    // positive dot (warp 0)
    if (warp == 0) {
        float s = 0.f;
#pragma unroll
        for (int j = 0; j < 4; j++) s += qsh[lane * 4 + j] * ksh[lane * 4 + j];
#pragma unroll
        for (int m = 16; m >= 1; m >>= 1) s += __shfl_xor_sync(0xffffffffu, s, m);
        if (lane == 0) sdots[NEG] = s;
    }

    // negatives: 2 per warp-iteration, 16 lanes each (uint4 = 8 halves/lane)
#pragma unroll 4
    for (int it = 0; it < 16; it++) {
        int n   = warp * 32 + it * 2 + half;
        int rw  = sidx[n];
        uint4 v = *(const uint4*)(g_embh + (size_t)rw * D + hl * 8);
        __half2* h2 = (__half2*)&v;
        float s = 0.f;
#pragma unroll
        for (int j = 0; j < 4; j++) {
            float2 f = __half22float2(h2[j]);
            s = fmaf(qr[2 * j],     f.x, s);
            s = fmaf(qr[2 * j + 1], f.y, s);
        }
        s += __shfl_xor_sync(0xffffffffu, s, 8);
        s += __shfl_xor_sync(0xffffffffu, s, 4);
        s += __shfl_xor_sync(0xffffffffu, s, 2);
        s += __shfl_xor_sync(0xffffffffu, s, 1);
        if (hl == 0) sdots[n] = s;
    }
    __syncthreads();

    const float invT = 1.0f / TEMPF;

    float v = sdots[tid];
    float mv = (tid == 0) ? fmaxf(v, sdots[NEG]) : v;
#pragma unroll
    for (int m = 16; m >= 1; m >>= 1) mv = fmaxf(mv, __shfl_xor_sync(0xffffffffu, mv, m));
    if (lane == 0) sred[warp] = mv;
    __syncthreads();
    if (tid == 0) {
        float m2 = sred[0];
#pragma unroll
        for (int i = 1; i < 8; i++) m2 = fmaxf(m2, sred[i]);
        sred[8] = m2;
    }
    __syncthreads();
    float ml = sred[8] * invT;

    float e = expf(v * invT - ml);
    if (tid == 0) e += expf(sdots[NEG] * invT - ml);
#pragma unroll
    for (int m = 16; m >= 1; m >>= 1) e += __shfl_xor_sync(0xffffffffu, e, m);
    if (lane == 0) sred[warp] = e;
    __syncthreads();
    if (tid == 0) {
        float s = 0.f;
#pragma unroll
        for (int i = 0; i < 8; i++) s += sred[i];
        g_losses[br * PP + p] = ml + logf(s) - sdots[NEG] * invT;
    }
}

// ---------------------------------------------------------------------------
// Kernel 3: deterministic mean reduction, out = mean0 + 0.1 * mean1
// ---------------------------------------------------------------------------
__global__ void finalize_kernel(float* __restrict__ out) {
    __shared__ double s0sh[256], s1sh[256];
    int tid = threadIdx.x;
    double s0 = 0.0, s1 = 0.0;
    for (int i = tid; i < PP; i += 256) {
        s0 += (double)g_losses[i];
        s1 += (double)g_losses[PP + i];
    }
    s0sh[tid] = s0; s1sh[tid] = s1;
    __syncthreads();
    for (int st = 128; st > 0; st >>= 1) {
        if (tid < st) { s0sh[tid] += s0sh[tid + st]; s1sh[tid] += s1sh[tid + st]; }
        __syncthreads();
    }
    if (tid == 0)
        out[0] = (float)(s0sh[0] / (double)PP + 0.1 * (s1sh[0] / (double)PP));
}

extern "C" void kernel_launch(void* const* d_in, const int* in_sizes, int n_in,
                              void* d_out, int out_size) {
    const float* X  = (const float*)d_in[0];
    const float* W  = (const float*)d_in[1];
    const float* b  = (const float*)d_in[2];
    const int*   pa = (const int*)d_in[3];
    const int*   pp = (const int*)d_in[4];
    const int*   ni = (const int*)d_in[5];
    const int*   wa = (const int*)d_in[6];
    const int*   wp = (const int*)d_in[7];
    const int*   wn = (const int*)d_in[8];
    float* out = (float*)d_out;

    cudaFuncSetAttribute(gemm_kernel, cudaFuncAttributeMaxDynamicSharedMemorySize, GEMM_SMEM);

    int nblocks = (NROWS + RPB - 1) / RPB;   // 1563
    gemm_kernel<<<nblocks, 256, GEMM_SMEM>>>(X, W, b);
    branch_kernel<<<dim3(PP, 2), 256>>>(pa, pp, ni, wa, wp, wn);
    finalize_kernel<<<1, 256>>>(out);
}

// round 8
// speedup vs baseline: 1.8120x; 1.4250x over previous
#include <cuda_runtime.h>
#include <cuda_fp16.h>
#include <cstdint>

#define NROWS 100000
#define D     128
#define PP    8192
#define NEG   256
#define TEMPF 0.07f

// Scratch (device globals: allocation-free per harness rules)
__device__ __align__(16) __half g_embh[ (size_t)NROWS * D ];   // fp16 projected embeddings
__device__ float g_losses[2 * PP];

// ---------------------------------------------------------------------------
// Kernel 1: embh = fp16(X @ W^T + b) via mma.sync.m16n8k16 (fp16 in, fp32 acc)
// CTA = 128 rows x 128 dims, 256 threads = 8 warps (2 m-groups x 4 n-groups),
// warp tile m64 x n32. X and W staged to smem as fp16 with 272B row pitch
// (conflict-free ldmatrix). k = 128 in 8 unrolled k16 steps.
// ---------------------------------------------------------------------------
#define XPITCH 272                       // bytes per smem row (136 halves)
#define XBYTES (128 * XPITCH)            // 34816
#define SM_X   0
#define SM_W   XBYTES
#define SM_B   (2 * XBYTES)              // bias, 512 B
#define GEMM_SMEM (2 * XBYTES + 512)     // 70144 B

#define LDSM4(d, addr) \
    asm volatile("ldmatrix.sync.aligned.m8n8.x4.shared.b16 {%0,%1,%2,%3}, [%4];" \
        : "=r"((d)[0]), "=r"((d)[1]), "=r"((d)[2]), "=r"((d)[3]) : "r"(addr))

#define MMA16816(c, a, b0, b1) \
    asm volatile("mma.sync.aligned.m16n8k16.row.col.f32.f16.f16.f32 " \
        "{%0,%1,%2,%3},{%4,%5,%6,%7},{%8,%9},{%0,%1,%2,%3};" \
        : "+f"((c)[0]), "+f"((c)[1]), "+f"((c)[2]), "+f"((c)[3]) \
        : "r"((a)[0]), "r"((a)[1]), "r"((a)[2]), "r"((a)[3]), "r"(b0), "r"(b1))

__global__ void __launch_bounds__(256, 2) gemm_kernel(const float* __restrict__ X,
                                                      const float* __restrict__ W,
                                                      const float* __restrict__ b) {
    extern __shared__ char sh[];
    float* bsm = (float*)(sh + SM_B);

    int tid  = threadIdx.x;
    int lane = tid & 31;
    int warp = tid >> 5;

    int row0 = blockIdx.x * 128;

    // ---- stage X (fp32 -> fp16, pitch 272B) ----
    for (int i = tid; i < 128 * 32; i += 256) {
        int rr = i >> 5, c4 = i & 31;
        int gr = row0 + rr;
        if (gr >= NROWS) gr = NROWS - 1;                 // clamp; stores guarded later
        float4 v = __ldg((const float4*)(X + (size_t)gr * D) + c4);
        __half2 h0 = __floats2half2_rn(v.x, v.y);
        __half2 h1 = __floats2half2_rn(v.z, v.w);
        *(uint2*)(sh + SM_X + rr * XPITCH + c4 * 8) =
            make_uint2(*(uint32_t*)&h0, *(uint32_t*)&h1);
    }
    // ---- stage W (fp32 -> fp16, pitch 272B); W[d][k] row-major = B col-major ----
    for (int i = tid; i < 128 * 32; i += 256) {
        int rr = i >> 5, c4 = i & 31;
        float4 v = __ldg((const float4*)(W + (size_t)rr * D) + c4);
        __half2 h0 = __floats2half2_rn(v.x, v.y);
        __half2 h1 = __floats2half2_rn(v.z, v.w);
        *(uint2*)(sh + SM_W + rr * XPITCH + c4 * 8) =
            make_uint2(*(uint32_t*)&h0, *(uint32_t*)&h1);
    }
    if (tid < D) bsm[tid] = b[tid];
    __syncthreads();

    int wm  = warp >> 2;          // 0..1  (m offset wm*64)
    int wn  = warp & 3;           // 0..3  (n offset wn*32)
    int n_b = wn * 32;

    int q = lane >> 3;            // ldmatrix matrix index
    int r = lane & 7;             // row within 8x8 matrix
    int g = lane >> 2;            // mma group row
    int t = lane & 3;             // mma col pair

    uint32_t xsh_u = (uint32_t)__cvta_generic_to_shared(sh + SM_X);
    uint32_t wsh_u = (uint32_t)__cvta_generic_to_shared(sh + SM_W);

    // A: matrices {m0-7,kLo}, {m8-15,kLo}, {m0-7,kHi}, {m8-15,kHi}
    uint32_t aBase = xsh_u + (uint32_t)((wm * 64 + (q & 1) * 8 + r) * XPITCH + (q >> 1) * 16);
    // B: matrices {nt0,kLo}, {nt0,kHi}, {nt1,kLo}, {nt1,kHi}
    uint32_t bBase = wsh_u + (uint32_t)((n_b + (q >> 1) * 8 + r) * XPITCH + (q & 1) * 16);

    float acc[4][4][4];
#pragma unroll
    for (int mt = 0; mt < 4; mt++)
#pragma unroll
        for (int nt = 0; nt < 4; nt++)
#pragma unroll
            for (int j = 0; j < 4; j++) acc[mt][nt][j] = 0.f;

#pragma unroll
    for (int ks = 0; ks < 8; ks++) {
        uint32_t A[4][4], B[2][4];
#pragma unroll
        for (int mt = 0; mt < 4; mt++)
            LDSM4(A[mt], aBase + mt * 16 * XPITCH + ks * 32);
#pragma unroll
        for (int np = 0; np < 2; np++)
            LDSM4(B[np], bBase + np * 16 * XPITCH + ks * 32);
#pragma unroll
        for (int mt = 0; mt < 4; mt++)
#pragma unroll
            for (int nt = 0; nt < 4; nt++)
                MMA16816(acc[mt][nt], A[mt], B[nt >> 1][(nt & 1) * 2], B[nt >> 1][(nt & 1) * 2 + 1]);
    }

    // ---- epilogue: + bias, fp16 store ----
#pragma unroll
    for (int nt = 0; nt < 4; nt++) {
        float2 bb = *(float2*)(bsm + n_b + nt * 8 + 2 * t);
        int col = n_b + nt * 8 + 2 * t;
#pragma unroll
        for (int mt = 0; mt < 4; mt++) {
            int rA = row0 + wm * 64 + mt * 16 + g;
            int rB = rA + 8;
            if (rA < NROWS) {
                __half2 h = __floats2half2_rn(acc[mt][nt][0] + bb.x, acc[mt][nt][1] + bb.y);
                *(__half2*)(g_embh + (size_t)rA * D + col) = h;
            }
            if (rB < NROWS) {
                __half2 h = __floats2half2_rn(acc[mt][nt][2] + bb.x, acc[mt][nt][3] + bb.y);
                *(__half2*)(g_embh + (size_t)rB * D + col) = h;
            }
        }
    }
}

// ---------------------------------------------------------------------------
// Kernel 2: per (p, branch): logits, logsumexp, per-pair loss.
// q,k,negatives all from fp16 embeddings; fp32 dot accumulation.
// ---------------------------------------------------------------------------
__global__ void branch_kernel(const int* __restrict__ pos_anchor,
                              const int* __restrict__ pos_partner,
                              const int* __restrict__ neg_idx,
                              const int* __restrict__ weak_anchor,
                              const int* __restrict__ weak_partner,
                              const int* __restrict__ weak_neg_idx) {
    __shared__ float qsh[D], ksh[D];
    __shared__ int   sidx[NEG];
    __shared__ float sdots[NEG + 1];
    __shared__ float sred[9];

    int p  = blockIdx.x;
    int br = blockIdx.y;
    const int* anc = br ? weak_anchor  : pos_anchor;
    const int* par = br ? weak_partner : pos_partner;
    const int* nix = br ? weak_neg_idx : neg_idx;

    int tid  = threadIdx.x;
    int lane = tid & 31;
    int warp = tid >> 5;

    int a  = anc[p];
    int pr = par[p];
    if (tid < D) qsh[tid]     = __half2float(g_embh[(size_t)a  * D + tid]);
    else         ksh[tid - D] = __half2float(g_embh[(size_t)pr * D + (tid - D)]);
    sidx[tid] = nix[(size_t)p * NEG + tid];
    __syncthreads();

    int hl   = lane & 15;
    int half = lane >> 4;

    float qr[8];
#pragma unroll
    for (int j = 0; j < 8; j++) qr[j] = qsh[hl * 8 + j];

    // positive dot (warp 0)
    if (warp == 0) {
        float s = 0.f;
#pragma unroll
        for (int j = 0; j < 4; j++) s += qsh[lane * 4 + j] * ksh[lane * 4 + j];
#pragma unroll
        for (int m = 16; m >= 1; m >>= 1) s += __shfl_xor_sync(0xffffffffu, s, m);
        if (lane == 0) sdots[NEG] = s;
    }

    // negatives: 2 per warp-iteration, 16 lanes each (uint4 = 8 halves/lane)
#pragma unroll 4
    for (int it = 0; it < 16; it++) {
        int n   = warp * 32 + it * 2 + half;
        int rw  = sidx[n];
        uint4 v = *(const uint4*)(g_embh + (size_t)rw * D + hl * 8);
        __half2* h2 = (__half2*)&v;
        float s = 0.f;
#pragma unroll
        for (int j = 0; j < 4; j++) {
            float2 f = __half22float2(h2[j]);
            s = fmaf(qr[2 * j],     f.x, s);
            s = fmaf(qr[2 * j + 1], f.y, s);
        }
        s += __shfl_xor_sync(0xffffffffu, s, 8);
        s += __shfl_xor_sync(0xffffffffu, s, 4);
        s += __shfl_xor_sync(0xffffffffu, s, 2);
        s += __shfl_xor_sync(0xffffffffu, s, 1);
        if (hl == 0) sdots[n] = s;
    }
    __syncthreads();

    const float invT = 1.0f / TEMPF;

    float v = sdots[tid];
    float mv = (tid == 0) ? fmaxf(v, sdots[NEG]) : v;
#pragma unroll
    for (int m = 16; m >= 1; m >>= 1) mv = fmaxf(mv, __shfl_xor_sync(0xffffffffu, mv, m));
    if (lane == 0) sred[warp] = mv;
    __syncthreads();
    if (tid == 0) {
        float m2 = sred[0];
#pragma unroll
        for (int i = 1; i < 8; i++) m2 = fmaxf(m2, sred[i]);
        sred[8] = m2;
    }
    __syncthreads();
    float ml = sred[8] * invT;

    float e = expf(v * invT - ml);
    if (tid == 0) e += expf(sdots[NEG] * invT - ml);
#pragma unroll
    for (int m = 16; m >= 1; m >>= 1) e += __shfl_xor_sync(0xffffffffu, e, m);
    if (lane == 0) sred[warp] = e;
    __syncthreads();
    if (tid == 0) {
        float s = 0.f;
#pragma unroll
        for (int i = 0; i < 8; i++) s += sred[i];
        g_losses[br * PP + p] = ml + logf(s) - sdots[NEG] * invT;
    }
}

// ---------------------------------------------------------------------------
// Kernel 3: deterministic mean reduction, out = mean0 + 0.1 * mean1
// ---------------------------------------------------------------------------
__global__ void finalize_kernel(float* __restrict__ out) {
    __shared__ double s0sh[256], s1sh[256];
    int tid = threadIdx.x;
    double s0 = 0.0, s1 = 0.0;
    for (int i = tid; i < PP; i += 256) {
        s0 += (double)g_losses[i];
        s1 += (double)g_losses[PP + i];
    }
    s0sh[tid] = s0; s1sh[tid] = s1;
    __syncthreads();
    for (int st = 128; st > 0; st >>= 1) {
        if (tid < st) { s0sh[tid] += s0sh[tid + st]; s1sh[tid] += s1sh[tid + st]; }
        __syncthreads();
    }
    if (tid == 0)
        out[0] = (float)(s0sh[0] / (double)PP + 0.1 * (s1sh[0] / (double)PP));
}

extern "C" void kernel_launch(void* const* d_in, const int* in_sizes, int n_in,
                              void* d_out, int out_size) {
    const float* X  = (const float*)d_in[0];
    const float* W  = (const float*)d_in[1];
    const float* b  = (const float*)d_in[2];
    const int*   pa = (const int*)d_in[3];
    const int*   pp = (const int*)d_in[4];
    const int*   ni = (const int*)d_in[5];
    const int*   wa = (const int*)d_in[6];
    const int*   wp = (const int*)d_in[7];
    const int*   wn = (const int*)d_in[8];
    float* out = (float*)d_out;

    cudaFuncSetAttribute(gemm_kernel, cudaFuncAttributeMaxDynamicSharedMemorySize, GEMM_SMEM);

    int nblocks = (NROWS + 127) / 128;   // 782
    gemm_kernel<<<nblocks, 256, GEMM_SMEM>>>(X, W, b);
    branch_kernel<<<dim3(PP, 2), 256>>>(pa, pp, ni, wa, wp, wn);
    finalize_kernel<<<1, 256>>>(out);
}

// round 9
// speedup vs baseline: 2.0386x; 1.1251x over previous
#include <cuda_runtime.h>
#include <cuda_fp16.h>
#include <cstdint>

#define NROWS 100000
#define D     128
#define PP    8192
#define NEG   256
#define TEMPF 0.07f
#define NTILES 782          // ceil(100000/128)

// Scratch (device globals: allocation-free per harness rules)
__device__ __align__(16) __half g_embh[ (size_t)NROWS * D ];   // fp16 projected embeddings
__device__ float g_losses[2 * PP];

// ---------------------------------------------------------------------------
// Kernel 1: embh = fp16(X @ W^T + b) — persistent cp.async-pipelined HMMA.
// 148 CTAs x 512 threads (16 warps = 4m x 4n, warp tile m32 x n32).
// W (fp16, 272B pitch, ldmatrix-ready) staged once per CTA.
// X streamed fp32 via cp.async into a double buffer (pitch 136 floats,
// conflict-free LDS.64); tile t+1 streams while tile t computes.
// ---------------------------------------------------------------------------
#define WPITCH 272                       // W smem bytes/row (136 halves)
#define WBYTES (128 * WPITCH)            // 34816
#define XFP    136                       // X smem floats/row
#define XPB    (XFP * 4)                 // 544 B/row
#define XBUFB  (128 * XPB)               // 69632 per buffer
#define SM_W   0
#define SM_B   WBYTES                    // bias 512B
#define SM_X0  (WBYTES + 512)
#define SM_X1  (SM_X0 + XBUFB)
#define GEMM_SMEM (SM_X1 + XBUFB)        // 174592 B

#define LDSM4(d, addr) \
    asm volatile("ldmatrix.sync.aligned.m8n8.x4.shared.b16 {%0,%1,%2,%3}, [%4];" \
        : "=r"((d)[0]), "=r"((d)[1]), "=r"((d)[2]), "=r"((d)[3]) : "r"(addr))

#define MMA16816(c, a, b0, b1) \
    asm volatile("mma.sync.aligned.m16n8k16.row.col.f32.f16.f16.f32 " \
        "{%0,%1,%2,%3},{%4,%5,%6,%7},{%8,%9},{%0,%1,%2,%3};" \
        : "+f"((c)[0]), "+f"((c)[1]), "+f"((c)[2]), "+f"((c)[3]) \
        : "r"((a)[0]), "r"((a)[1]), "r"((a)[2]), "r"((a)[3]), "r"(b0), "r"(b1))

#define CP16(dst, src) \
    asm volatile("cp.async.cg.shared.global [%0], [%1], 16;" :: "r"(dst), "l"(src))

__device__ __forceinline__ uint32_t packh2(float lo, float hi) {
    __half2 h = __floats2half2_rn(lo, hi);
    return *(uint32_t*)&h;
}

__global__ void __launch_bounds__(512, 1) gemm_kernel(const float* __restrict__ X,
                                                      const float* __restrict__ W,
                                                      const float* __restrict__ b) {
    extern __shared__ char sh[];
    float* bsm = (float*)(sh + SM_B);

    int tid  = threadIdx.x;
    int lane = tid & 31;
    int warp = tid >> 5;

    // ---- stage W once (fp32 -> fp16, 272B pitch, ldmatrix layout) ----
    for (int i = tid; i < 128 * 32; i += 512) {
        int rr = i >> 5, c4 = i & 31;
        float4 v = __ldg((const float4*)(W + (size_t)rr * D) + c4);
        *(uint2*)(sh + SM_W + rr * WPITCH + c4 * 8) =
            make_uint2(packh2(v.x, v.y), packh2(v.z, v.w));
    }
    if (tid < D) bsm[tid] = b[tid];

    uint32_t wsh_u = (uint32_t)__cvta_generic_to_shared(sh + SM_W);
    uint32_t x0_u  = (uint32_t)__cvta_generic_to_shared(sh + SM_X0);

    int wm = warp >> 2;           // 0..3, m offset wm*32
    int wn = warp & 3;            // 0..3, n offset wn*32
    int n_b = wn * 32;

    int q = lane >> 3;            // ldmatrix matrix index
    int r = lane & 7;
    int g = lane >> 2;            // mma group row
    int t = lane & 3;             // mma col pair

    // B ldmatrix base (same as validated R7 layout)
    uint32_t bBase = wsh_u + (uint32_t)((n_b + (q >> 1) * 8 + r) * WPITCH + (q & 1) * 16);

    // issue cp.async for one X tile (4096 x 16B chunks / 512 thr = 8 per thread)
    auto issue_x = [&](uint32_t xbuf, int tile) {
        int row0 = tile * 128;
#pragma unroll
        for (int it = 0; it < 8; it++) {
            int idx = it * 512 + tid;
            int rr = idx >> 5, cc = idx & 31;
            int gr = row0 + rr;
            if (gr >= NROWS) gr = NROWS - 1;            // clamp; stores guarded
            const float* src = X + (size_t)gr * D + cc * 4;
            CP16(xbuf + rr * XPB + cc * 16, src);
        }
    };

    int t0 = blockIdx.x;
    if (t0 < NTILES) issue_x(x0_u, t0);
    asm volatile("cp.async.commit_group;" ::: "memory");
    __syncthreads();   // W + bias visible (also orders first-buffer reuse)

    int bufsel = 0;
    for (int tile = t0; tile < NTILES; tile += 148) {
        uint32_t xcur = bufsel ? (x0_u + XBUFB) : x0_u;
        uint32_t xnxt = bufsel ? x0_u : (x0_u + XBUFB);

        int tn = tile + 148;
        if (tn < NTILES) issue_x(xnxt, tn);
        asm volatile("cp.async.commit_group;" ::: "memory");
        asm volatile("cp.async.wait_group 1;" ::: "memory");   // tile's data landed
        __syncthreads();

        // ---- compute 128x128 tile ----
        const float* Xb = (const float*)(sh + (xcur - (uint32_t)__cvta_generic_to_shared(sh)));
        // (generic pointer to current X buffer)
        float acc[2][4][4];
#pragma unroll
        for (int mt = 0; mt < 2; mt++)
#pragma unroll
            for (int nt = 0; nt < 4; nt++)
#pragma unroll
                for (int j = 0; j < 4; j++) acc[mt][nt][j] = 0.f;

        int m_b = wm * 32;
#pragma unroll
        for (int ks = 0; ks < 8; ks++) {
            uint32_t A[2][4], B[2][4];
#pragma unroll
            for (int mt = 0; mt < 2; mt++) {
                const float* p0 = Xb + (m_b + mt * 16 + g) * XFP + ks * 16 + 2 * t;
                const float* p1 = p0 + 8 * XFP;
                float2 v0 = *(const float2*)p0;         // A[g][2t..]
                float2 v1 = *(const float2*)p1;         // A[g+8][2t..]
                float2 v2 = *(const float2*)(p0 + 8);   // A[g][2t+8..]
                float2 v3 = *(const float2*)(p1 + 8);   // A[g+8][2t+8..]
                A[mt][0] = packh2(v0.x, v0.y);
                A[mt][1] = packh2(v1.x, v1.y);
                A[mt][2] = packh2(v2.x, v2.y);
                A[mt][3] = packh2(v3.x, v3.y);
            }
#pragma unroll
            for (int np = 0; np < 2; np++)
                LDSM4(B[np], bBase + np * 16 * WPITCH + ks * 32);
#pragma unroll
            for (int mt = 0; mt < 2; mt++)
#pragma unroll
                for (int nt = 0; nt < 4; nt++)
                    MMA16816(acc[mt][nt], A[mt],
                             B[nt >> 1][(nt & 1) * 2], B[nt >> 1][(nt & 1) * 2 + 1]);
        }

        // ---- epilogue: + bias, fp16 store ----
        int row0 = tile * 128;
#pragma unroll
        for (int nt = 0; nt < 4; nt++) {
            int col = n_b + nt * 8 + 2 * t;
            float2 bb = *(float2*)(bsm + col);
#pragma unroll
            for (int mt = 0; mt < 2; mt++) {
                int rA = row0 + m_b + mt * 16 + g;
                int rB = rA + 8;
                if (rA < NROWS) {
                    __half2 h = __floats2half2_rn(acc[mt][nt][0] + bb.x, acc[mt][nt][1] + bb.y);
                    *(__half2*)(g_embh + (size_t)rA * D + col) = h;
                }
                if (rB < NROWS) {
                    __half2 h = __floats2half2_rn(acc[mt][nt][2] + bb.x, acc[mt][nt][3] + bb.y);
                    *(__half2*)(g_embh + (size_t)rB * D + col) = h;
                }
            }
        }
        __syncthreads();   // everyone done reading xcur before it is refilled
        bufsel ^= 1;
    }
}

// ---------------------------------------------------------------------------
// Kernel 2: per (p, branch): logits, logsumexp, per-pair loss.
// q,k,negatives all from fp16 embeddings; fp32 dot accumulation.
// ---------------------------------------------------------------------------
__global__ void branch_kernel(const int* __restrict__ pos_anchor,
                              const int* __restrict__ pos_partner,
                              const int* __restrict__ neg_idx,
                              const int* __restrict__ weak_anchor,
                              const int* __restrict__ weak_partner,
                              const int* __restrict__ weak_neg_idx) {
    __shared__ float qsh[D], ksh[D];
    __shared__ int   sidx[NEG];
    __shared__ float sdots[NEG + 1];
    __shared__ float sred[9];

    int p  = blockIdx.x;
    int br = blockIdx.y;
    const int* anc = br ? weak_anchor  : pos_anchor;
    const int* par = br ? weak_partner : pos_partner;
    const int* nix = br ? weak_neg_idx : neg_idx;

    int tid  = threadIdx.x;
    int lane = tid & 31;
    int warp = tid >> 5;

    int a  = anc[p];
    int pr = par[p];
    if (tid < D) qsh[tid]     = __half2float(g_embh[(size_t)a  * D + tid]);
    else         ksh[tid - D] = __half2float(g_embh[(size_t)pr * D + (tid - D)]);
    sidx[tid] = nix[(size_t)p * NEG + tid];
    __syncthreads();

    int hl   = lane & 15;
    int half = lane >> 4;

    float qr[8];
#pragma unroll
    for (int j = 0; j < 8; j++) qr[j] = qsh[hl * 8 + j];

    // positive dot (warp 0)
    if (warp == 0) {
        float s = 0.f;
#pragma unroll
        for (int j = 0; j < 4; j++) s += qsh[lane * 4 + j] * ksh[lane * 4 + j];
#pragma unroll
        for (int m = 16; m >= 1; m >>= 1) s += __shfl_xor_sync(0xffffffffu, s, m);
        if (lane == 0) sdots[NEG] = s;
    }

    // negatives: 2 per warp-iteration, 16 lanes each (uint4 = 8 halves/lane)
#pragma unroll 4
    for (int it = 0; it < 16; it++) {
        int n   = warp * 32 + it * 2 + half;
        int rw  = sidx[n];
        uint4 v = *(const uint4*)(g_embh + (size_t)rw * D + hl * 8);
        __half2* h2 = (__half2*)&v;
        float s = 0.f;
#pragma unroll
        for (int j = 0; j < 4; j++) {
            float2 f = __half22float2(h2[j]);
            s = fmaf(qr[2 * j],     f.x, s);
            s = fmaf(qr[2 * j + 1], f.y, s);
        }
        s += __shfl_xor_sync(0xffffffffu, s, 8);
        s += __shfl_xor_sync(0xffffffffu, s, 4);
        s += __shfl_xor_sync(0xffffffffu, s, 2);
        s += __shfl_xor_sync(0xffffffffu, s, 1);
        if (hl == 0) sdots[n] = s;
    }
    __syncthreads();

    const float invT = 1.0f / TEMPF;

    float v = sdots[tid];
    float mv = (tid == 0) ? fmaxf(v, sdots[NEG]) : v;
#pragma unroll
    for (int m = 16; m >= 1; m >>= 1) mv = fmaxf(mv, __shfl_xor_sync(0xffffffffu, mv, m));
    if (lane == 0) sred[warp] = mv;
    __syncthreads();
    if (tid == 0) {
        float m2 = sred[0];
#pragma unroll
        for (int i = 1; i < 8; i++) m2 = fmaxf(m2, sred[i]);
        sred[8] = m2;
    }
    __syncthreads();
    float ml = sred[8] * invT;

    float e = expf(v * invT - ml);
    if (tid == 0) e += expf(sdots[NEG] * invT - ml);
#pragma unroll
    for (int m = 16; m >= 1; m >>= 1) e += __shfl_xor_sync(0xffffffffu, e, m);
    if (lane == 0) sred[warp] = e;
    __syncthreads();
    if (tid == 0) {
        float s = 0.f;
#pragma unroll
        for (int i = 0; i < 8; i++) s += sred[i];
        g_losses[br * PP + p] = ml + logf(s) - sdots[NEG] * invT;
    }
}

// ---------------------------------------------------------------------------
// Kernel 3: deterministic mean reduction, out = mean0 + 0.1 * mean1
// ---------------------------------------------------------------------------
__global__ void finalize_kernel(float* __restrict__ out) {
    __shared__ double s0sh[256], s1sh[256];
    int tid = threadIdx.x;
    double s0 = 0.0, s1 = 0.0;
    for (int i = tid; i < PP; i += 256) {
        s0 += (double)g_losses[i];
        s1 += (double)g_losses[PP + i];
    }
    s0sh[tid] = s0; s1sh[tid] = s1;
    __syncthreads();
    for (int st = 128; st > 0; st >>= 1) {
        if (tid < st) { s0sh[tid] += s0sh[tid + st]; s1sh[tid] += s1sh[tid + st]; }
        __syncthreads();
    }
    if (tid == 0)
        out[0] = (float)(s0sh[0] / (double)PP + 0.1 * (s1sh[0] / (double)PP));
}

extern "C" void kernel_launch(void* const* d_in, const int* in_sizes, int n_in,
                              void* d_out, int out_size) {
    const float* X  = (const float*)d_in[0];
    const float* W  = (const float*)d_in[1];
    const float* b  = (const float*)d_in[2];
    const int*   pa = (const int*)d_in[3];
    const int*   pp = (const int*)d_in[4];
    const int*   ni = (const int*)d_in[5];
    const int*   wa = (const int*)d_in[6];
    const int*   wp = (const int*)d_in[7];
    const int*   wn = (const int*)d_in[8];
    float* out = (float*)d_out;

    cudaFuncSetAttribute(gemm_kernel, cudaFuncAttributeMaxDynamicSharedMemorySize, GEMM_SMEM);

    gemm_kernel<<<148, 512, GEMM_SMEM>>>(X, W, b);
    branch_kernel<<<dim3(PP, 2), 256>>>(pa, pp, ni, wa, wp, wn);
    finalize_kernel<<<1, 256>>>(out);
}

// round 10
// speedup vs baseline: 2.1310x; 1.0453x over previous
#include <cuda_runtime.h>
#include <cuda_fp16.h>
#include <cstdint>

#define NROWS 100000
#define D     128
#define PP    8192
#define NEG   256
#define TEMPF 0.07f
#define NTILES 782          // ceil(100000/128)

// Scratch (device globals: allocation-free per harness rules)
__device__ __align__(16) __half  g_embh [ (size_t)NROWS * D ];  // fp16 projected embeddings
__device__ __align__(16) int8_t  g_embi8[ (size_t)NROWS * D ];  // int8 quantized rows
__device__ float g_scale[NROWS];                                // per-row dequant scale
__device__ float g_losses[2 * PP];

// ---------------------------------------------------------------------------
// Kernel 1: embh = fp16(X @ W^T + b) — persistent cp.async-pipelined HMMA.
// (unchanged from R8: 28.3us, ~2x memory floor)
// ---------------------------------------------------------------------------
#define WPITCH 272
#define WBYTES (128 * WPITCH)
#define XFP    136
#define XPB    (XFP * 4)
#define XBUFB  (128 * XPB)
#define SM_W   0
#define SM_B   WBYTES
#define SM_X0  (WBYTES + 512)
#define SM_X1  (SM_X0 + XBUFB)
#define GEMM_SMEM (SM_X1 + XBUFB)        // 174592 B

#define LDSM4(d, addr) \
    asm volatile("ldmatrix.sync.aligned.m8n8.x4.shared.b16 {%0,%1,%2,%3}, [%4];" \
        : "=r"((d)[0]), "=r"((d)[1]), "=r"((d)[2]), "=r"((d)[3]) : "r"(addr))

#define MMA16816(c, a, b0, b1) \
    asm volatile("mma.sync.aligned.m16n8k16.row.col.f32.f16.f16.f32 " \
        "{%0,%1,%2,%3},{%4,%5,%6,%7},{%8,%9},{%0,%1,%2,%3};" \
        : "+f"((c)[0]), "+f"((c)[1]), "+f"((c)[2]), "+f"((c)[3]) \
        : "r"((a)[0]), "r"((a)[1]), "r"((a)[2]), "r"((a)[3]), "r"(b0), "r"(b1))

#define CP16(dst, src) \
    asm volatile("cp.async.cg.shared.global [%0], [%1], 16;" :: "r"(dst), "l"(src))

__device__ __forceinline__ uint32_t packh2(float lo, float hi) {
    __half2 h = __floats2half2_rn(lo, hi);
    return *(uint32_t*)&h;
}

__global__ void __launch_bounds__(512, 1) gemm_kernel(const float* __restrict__ X,
                                                      const float* __restrict__ W,
                                                      const float* __restrict__ b) {
    extern __shared__ char sh[];
    float* bsm = (float*)(sh + SM_B);

    int tid  = threadIdx.x;
    int lane = tid & 31;
    int warp = tid >> 5;

    for (int i = tid; i < 128 * 32; i += 512) {
        int rr = i >> 5, c4 = i & 31;
        float4 v = __ldg((const float4*)(W + (size_t)rr * D) + c4);
        *(uint2*)(sh + SM_W + rr * WPITCH + c4 * 8) =
            make_uint2(packh2(v.x, v.y), packh2(v.z, v.w));
    }
    if (tid < D) bsm[tid] = b[tid];

    uint32_t wsh_u = (uint32_t)__cvta_generic_to_shared(sh + SM_W);
    uint32_t x0_u  = (uint32_t)__cvta_generic_to_shared(sh + SM_X0);

    int wm = warp >> 2;
    int wn = warp & 3;
    int n_b = wn * 32;

    int q = lane >> 3;
    int r = lane & 7;
    int g = lane >> 2;
    int t = lane & 3;

    uint32_t bBase = wsh_u + (uint32_t)((n_b + (q >> 1) * 8 + r) * WPITCH + (q & 1) * 16);

    auto issue_x = [&](uint32_t xbuf, int tile) {
        int row0 = tile * 128;
#pragma unroll
        for (int it = 0; it < 8; it++) {
            int idx = it * 512 + tid;
            int rr = idx >> 5, cc = idx & 31;
            int gr = row0 + rr;
            if (gr >= NROWS) gr = NROWS - 1;
            const float* src = X + (size_t)gr * D + cc * 4;
            CP16(xbuf + rr * XPB + cc * 16, src);
        }
    };

    int t0 = blockIdx.x;
    if (t0 < NTILES) issue_x(x0_u, t0);
    asm volatile("cp.async.commit_group;" ::: "memory");
    __syncthreads();

    int bufsel = 0;
    for (int tile = t0; tile < NTILES; tile += 148) {
        uint32_t xcur = bufsel ? (x0_u + XBUFB) : x0_u;
        uint32_t xnxt = bufsel ? x0_u : (x0_u + XBUFB);

        int tn = tile + 148;
        if (tn < NTILES) issue_x(xnxt, tn);
        asm volatile("cp.async.commit_group;" ::: "memory");
        asm volatile("cp.async.wait_group 1;" ::: "memory");
        __syncthreads();

        const float* Xb = (const float*)(sh + (xcur - (uint32_t)__cvta_generic_to_shared(sh)));
        float acc[2][4][4];
#pragma unroll
        for (int mt = 0; mt < 2; mt++)
#pragma unroll
            for (int nt = 0; nt < 4; nt++)
#pragma unroll
                for (int j = 0; j < 4; j++) acc[mt][nt][j] = 0.f;

        int m_b = wm * 32;
#pragma unroll
        for (int ks = 0; ks < 8; ks++) {
            uint32_t A[2][4], B[2][4];
#pragma unroll
            for (int mt = 0; mt < 2; mt++) {
                const float* p0 = Xb + (m_b + mt * 16 + g) * XFP + ks * 16 + 2 * t;
                const float* p1 = p0 + 8 * XFP;
                float2 v0 = *(const float2*)p0;
                float2 v1 = *(const float2*)p1;
                float2 v2 = *(const float2*)(p0 + 8);
                float2 v3 = *(const float2*)(p1 + 8);
                A[mt][0] = packh2(v0.x, v0.y);
                A[mt][1] = packh2(v1.x, v1.y);
                A[mt][2] = packh2(v2.x, v2.y);
                A[mt][3] = packh2(v3.x, v3.y);
            }
#pragma unroll
            for (int np = 0; np < 2; np++)
                LDSM4(B[np], bBase + np * 16 * WPITCH + ks * 32);
#pragma unroll
            for (int mt = 0; mt < 2; mt++)
#pragma unroll
                for (int nt = 0; nt < 4; nt++)
                    MMA16816(acc[mt][nt], A[mt],
                             B[nt >> 1][(nt & 1) * 2], B[nt >> 1][(nt & 1) * 2 + 1]);
        }

        int row0 = tile * 128;
#pragma unroll
        for (int nt = 0; nt < 4; nt++) {
            int col = n_b + nt * 8 + 2 * t;
            float2 bb = *(float2*)(bsm + col);
#pragma unroll
            for (int mt = 0; mt < 2; mt++) {
                int rA = row0 + m_b + mt * 16 + g;
                int rB = rA + 8;
                if (rA < NROWS) {
                    __half2 h = __floats2half2_rn(acc[mt][nt][0] + bb.x, acc[mt][nt][1] + bb.y);
                    *(__half2*)(g_embh + (size_t)rA * D + col) = h;
                }
                if (rB < NROWS) {
                    __half2 h = __floats2half2_rn(acc[mt][nt][2] + bb.x, acc[mt][nt][3] + bb.y);
                    *(__half2*)(g_embh + (size_t)rB * D + col) = h;
                }
            }
        }
        __syncthreads();
        bufsel ^= 1;
    }
}

// ---------------------------------------------------------------------------
// Kernel 1b: per-row int8 quantization. Warp per row (12500 x 256 thr exact).
// lane loads 4 halves (8B), warp-max, round-to-nearest int8, packed store.
// ---------------------------------------------------------------------------
__global__ void __launch_bounds__(256) quant_kernel() {
    int lane = threadIdx.x & 31;
    int warp = threadIdx.x >> 5;
    int row  = blockIdx.x * 8 + warp;        // 12500*8 = 100000 exact

    uint2 v = *(const uint2*)(g_embh + (size_t)row * D + lane * 4);
    __half2 h0 = *(__half2*)&v.x;
    __half2 h1 = *(__half2*)&v.y;
    float f0 = __half2float(h0.x), f1 = __half2float(h0.y);
    float f2 = __half2float(h1.x), f3 = __half2float(h1.y);

    float m = fmaxf(fmaxf(fabsf(f0), fabsf(f1)), fmaxf(fabsf(f2), fabsf(f3)));
#pragma unroll
    for (int s = 16; s >= 1; s >>= 1) m = fmaxf(m, __shfl_xor_sync(0xffffffffu, m, s));

    float inv = 127.f / fmaxf(m, 1e-20f);
    int q0 = __float2int_rn(f0 * inv);
    int q1 = __float2int_rn(f1 * inv);
    int q2 = __float2int_rn(f2 * inv);
    int q3 = __float2int_rn(f3 * inv);
    uint32_t pk = (uint32_t)(q0 & 0xFF) | ((uint32_t)(q1 & 0xFF) << 8) |
                  ((uint32_t)(q2 & 0xFF) << 16) | ((uint32_t)(q3 & 0xFF) << 24);
    *(uint32_t*)(g_embi8 + (size_t)row * D + lane * 4) = pk;
    if (lane == 0) g_scale[row] = m * (1.f / 127.f);
}

// ---------------------------------------------------------------------------
// Kernel 2: per (p, branch): logits, logsumexp, per-pair loss.
// Negatives: int8 rows, dp4a exact int32 dot + REDUX; pos dot from fp16.
// ---------------------------------------------------------------------------
__global__ void branch_kernel(const int* __restrict__ pos_anchor,
                              const int* __restrict__ pos_partner,
                              const int* __restrict__ neg_idx,
                              const int* __restrict__ weak_anchor,
                              const int* __restrict__ weak_partner,
                              const int* __restrict__ weak_neg_idx) {
    __shared__ float qsh[D], ksh[D];
    __shared__ int   sidx[NEG];
    __shared__ float sscale[NEG];
    __shared__ float sdots[NEG + 1];
    __shared__ uint32_t qi8[32];
    __shared__ float sq_sh;
    __shared__ float sred[9];

    int p  = blockIdx.x;
    int br = blockIdx.y;
    const int* anc = br ? weak_anchor  : pos_anchor;
    const int* par = br ? weak_partner : pos_partner;
    const int* nix = br ? weak_neg_idx : neg_idx;

    int tid  = threadIdx.x;
    int lane = tid & 31;
    int warp = tid >> 5;

    int a  = anc[p];
    int pr = par[p];
    if (tid < D) qsh[tid]     = __half2float(g_embh[(size_t)a  * D + tid]);
    else         ksh[tid - D] = __half2float(g_embh[(size_t)pr * D + (tid - D)]);
    int si = nix[(size_t)p * NEG + tid];
    sidx[tid]   = si;
    sscale[tid] = g_scale[si];                 // same-thread pairing, no sync needed
    if (tid < 32) qi8[tid] = ((const uint32_t*)(g_embi8 + (size_t)a * D))[tid];
    if (tid == 0) sq_sh = g_scale[a];
    __syncthreads();

    int grp = lane >> 3;            // 0..3: negative within quad
    int gl  = lane & 7;             // lane within 8-lane group
    uint32_t gmask = 0xFFu << (grp * 8);

    uint32_t qp[4];
#pragma unroll
    for (int j = 0; j < 4; j++) qp[j] = qi8[gl * 4 + j];
    float sq = sq_sh;

    // positive dot (warp 0, fp16-accuracy path)
    if (warp == 0) {
        float s = 0.f;
#pragma unroll
        for (int j = 0; j < 4; j++) s += qsh[lane * 4 + j] * ksh[lane * 4 + j];
#pragma unroll
        for (int m = 16; m >= 1; m >>= 1) s += __shfl_xor_sync(0xffffffffu, s, m);
        if (lane == 0) sdots[NEG] = s;
    }

    // negatives: 4 per warp-iteration, 8 lanes each (uint4 = 16 int8/lane)
#pragma unroll
    for (int it = 0; it < 8; it++) {
        int n  = warp * 32 + it * 4 + grp;
        int rw = sidx[n];
        uint4 v = *(const uint4*)(g_embi8 + (size_t)rw * D + gl * 16);
        int isum = 0;
        isum = __dp4a((int)v.x, (int)qp[0], isum);
        isum = __dp4a((int)v.y, (int)qp[1], isum);
        isum = __dp4a((int)v.z, (int)qp[2], isum);
        isum = __dp4a((int)v.w, (int)qp[3], isum);
        isum = __reduce_add_sync(gmask, isum);
        if (gl == 0) sdots[n] = (float)isum * sq * sscale[n];
    }
    __syncthreads();

    const float invT = 1.0f / TEMPF;

    float v = sdots[tid];
    float mv = (tid == 0) ? fmaxf(v, sdots[NEG]) : v;
#pragma unroll
    for (int m = 16; m >= 1; m >>= 1) mv = fmaxf(mv, __shfl_xor_sync(0xffffffffu, mv, m));
    if (lane == 0) sred[warp] = mv;
    __syncthreads();
    if (tid == 0) {
        float m2 = sred[0];
#pragma unroll
        for (int i = 1; i < 8; i++) m2 = fmaxf(m2, sred[i]);
        sred[8] = m2;
    }
    __syncthreads();
    float ml = sred[8] * invT;

    float e = expf(v * invT - ml);
    if (tid == 0) e += expf(sdots[NEG] * invT - ml);
#pragma unroll
    for (int m = 16; m >= 1; m >>= 1) e += __shfl_xor_sync(0xffffffffu, e, m);
    if (lane == 0) sred[warp] = e;
    __syncthreads();
    if (tid == 0) {
        float s = 0.f;
#pragma unroll
        for (int i = 0; i < 8; i++) s += sred[i];
        g_losses[br * PP + p] = ml + logf(s) - sdots[NEG] * invT;
    }
}

// ---------------------------------------------------------------------------
// Kernel 3: deterministic mean reduction, out = mean0 + 0.1 * mean1
// ---------------------------------------------------------------------------
__global__ void finalize_kernel(float* __restrict__ out) {
    __shared__ double s0sh[256], s1sh[256];
    int tid = threadIdx.x;
    double s0 = 0.0, s1 = 0.0;
    for (int i = tid; i < PP; i += 256) {
        s0 += (double)g_losses[i];
        s1 += (double)g_losses[PP + i];
    }
    s0sh[tid] = s0; s1sh[tid] = s1;
    __syncthreads();
    for (int st = 128; st > 0; st >>= 1) {
        if (tid < st) { s0sh[tid] += s0sh[tid + st]; s1sh[tid] += s1sh[tid + st]; }
        __syncthreads();
    }
    if (tid == 0)
        out[0] = (float)(s0sh[0] / (double)PP + 0.1 * (s1sh[0] / (double)PP));
}

extern "C" void kernel_launch(void* const* d_in, const int* in_sizes, int n_in,
                              void* d_out, int out_size) {
    const float* X  = (const float*)d_in[0];
    const float* W  = (const float*)d_in[1];
    const float* b  = (const float*)d_in[2];
    const int*   pa = (const int*)d_in[3];
    const int*   pp = (const int*)d_in[4];
    const int*   ni = (const int*)d_in[5];
    const int*   wa = (const int*)d_in[6];
    const int*   wp = (const int*)d_in[7];
    const int*   wn = (const int*)d_in[8];
    float* out = (float*)d_out;

    cudaFuncSetAttribute(gemm_kernel, cudaFuncAttributeMaxDynamicSharedMemorySize, GEMM_SMEM);

    gemm_kernel<<<148, 512, GEMM_SMEM>>>(X, W, b);
    quant_kernel<<<NROWS / 8, 256>>>();               // 12500 blocks exact
    branch_kernel<<<dim3(PP, 2), 256>>>(pa, pp, ni, wa, wp, wn);
    finalize_kernel<<<1, 256>>>(out);
}

// round 11
// speedup vs baseline: 2.1653x; 1.0161x over previous
#include <cuda_runtime.h>
#include <cuda_fp16.h>
#include <cstdint>

#define NROWS 100000
#define D     128
#define PP    8192
#define NEG   256
#define TEMPF 0.07f
#define NTILES 782          // ceil(100000/128)

// Scratch (device globals: allocation-free per harness rules)
__device__ __align__(16) __half  g_embh [ (size_t)NROWS * D ];  // fp16 projected embeddings
__device__ __align__(16) int8_t  g_embi8[ (size_t)NROWS * D ];  // int8 quantized rows
__device__ unsigned g_gmax_bits;                                // global |emb| max (float bits)
__device__ float g_losses[2 * PP];

// ---------------------------------------------------------------------------
// Kernel 0: reset global max (graph replays must be deterministic)
// ---------------------------------------------------------------------------
__global__ void init_kernel() { g_gmax_bits = 0u; }

// ---------------------------------------------------------------------------
// Kernel 1: embh = fp16(X @ W^T + b) — persistent cp.async-pipelined HMMA.
// Epilogue additionally folds the global |emb| max via REDUX + atomicMax
// (int-punned non-negative float: exact, order-independent).
// ---------------------------------------------------------------------------
#define WPITCH 272
#define WBYTES (128 * WPITCH)
#define XFP    136
#define XPB    (XFP * 4)
#define XBUFB  (128 * XPB)
#define SM_W   0
#define SM_B   WBYTES
#define SM_X0  (WBYTES + 512)
#define SM_X1  (SM_X0 + XBUFB)
#define GEMM_SMEM (SM_X1 + XBUFB)        // 174592 B

#define LDSM4(d, addr) \
    asm volatile("ldmatrix.sync.aligned.m8n8.x4.shared.b16 {%0,%1,%2,%3}, [%4];" \
        : "=r"((d)[0]), "=r"((d)[1]), "=r"((d)[2]), "=r"((d)[3]) : "r"(addr))

#define MMA16816(c, a, b0, b1) \
    asm volatile("mma.sync.aligned.m16n8k16.row.col.f32.f16.f16.f32 " \
        "{%0,%1,%2,%3},{%4,%5,%6,%7},{%8,%9},{%0,%1,%2,%3};" \
        : "+f"((c)[0]), "+f"((c)[1]), "+f"((c)[2]), "+f"((c)[3]) \
        : "r"((a)[0]), "r"((a)[1]), "r"((a)[2]), "r"((a)[3]), "r"(b0), "r"(b1))

#define CP16(dst, src) \
    asm volatile("cp.async.cg.shared.global [%0], [%1], 16;" :: "r"(dst), "l"(src))

__device__ __forceinline__ uint32_t packh2(float lo, float hi) {
    __half2 h = __floats2half2_rn(lo, hi);
    return *(uint32_t*)&h;
}

__global__ void __launch_bounds__(512, 1) gemm_kernel(const float* __restrict__ X,
                                                      const float* __restrict__ W,
                                                      const float* __restrict__ b) {
    extern __shared__ char sh[];
    float* bsm = (float*)(sh + SM_B);

    int tid  = threadIdx.x;
    int lane = tid & 31;
    int warp = tid >> 5;

    for (int i = tid; i < 128 * 32; i += 512) {
        int rr = i >> 5, c4 = i & 31;
        float4 v = __ldg((const float4*)(W + (size_t)rr * D) + c4);
        *(uint2*)(sh + SM_W + rr * WPITCH + c4 * 8) =
            make_uint2(packh2(v.x, v.y), packh2(v.z, v.w));
    }
    if (tid < D) bsm[tid] = b[tid];

    uint32_t wsh_u = (uint32_t)__cvta_generic_to_shared(sh + SM_W);
    uint32_t x0_u  = (uint32_t)__cvta_generic_to_shared(sh + SM_X0);

    int wm = warp >> 2;
    int wn = warp & 3;
    int n_b = wn * 32;

    int q = lane >> 3;
    int r = lane & 7;
    int g = lane >> 2;
    int t = lane & 3;

    uint32_t bBase = wsh_u + (uint32_t)((n_b + (q >> 1) * 8 + r) * WPITCH + (q & 1) * 16);

    auto issue_x = [&](uint32_t xbuf, int tile) {
        int row0 = tile * 128;
#pragma unroll
        for (int it = 0; it < 8; it++) {
            int idx = it * 512 + tid;
            int rr = idx >> 5, cc = idx & 31;
            int gr = row0 + rr;
            if (gr >= NROWS) gr = NROWS - 1;
            const float* src = X + (size_t)gr * D + cc * 4;
            CP16(xbuf + rr * XPB + cc * 16, src);
        }
    };

    int t0 = blockIdx.x;
    if (t0 < NTILES) issue_x(x0_u, t0);
    asm volatile("cp.async.commit_group;" ::: "memory");
    __syncthreads();

    int bufsel = 0;
    for (int tile = t0; tile < NTILES; tile += 148) {
        uint32_t xcur = bufsel ? (x0_u + XBUFB) : x0_u;
        uint32_t xnxt = bufsel ? x0_u : (x0_u + XBUFB);

        int tn = tile + 148;
        if (tn < NTILES) issue_x(xnxt, tn);
        asm volatile("cp.async.commit_group;" ::: "memory");
        asm volatile("cp.async.wait_group 1;" ::: "memory");
        __syncthreads();

        const float* Xb = (const float*)(sh + (xcur - (uint32_t)__cvta_generic_to_shared(sh)));
        float acc[2][4][4];
#pragma unroll
        for (int mt = 0; mt < 2; mt++)
#pragma unroll
            for (int nt = 0; nt < 4; nt++)
#pragma unroll
                for (int j = 0; j < 4; j++) acc[mt][nt][j] = 0.f;

        int m_b = wm * 32;
#pragma unroll
        for (int ks = 0; ks < 8; ks++) {
            uint32_t A[2][4], B[2][4];
#pragma unroll
            for (int mt = 0; mt < 2; mt++) {
                const float* p0 = Xb + (m_b + mt * 16 + g) * XFP + ks * 16 + 2 * t;
                const float* p1 = p0 + 8 * XFP;
                float2 v0 = *(const float2*)p0;
                float2 v1 = *(const float2*)p1;
                float2 v2 = *(const float2*)(p0 + 8);
                float2 v3 = *(const float2*)(p1 + 8);
                A[mt][0] = packh2(v0.x, v0.y);
                A[mt][1] = packh2(v1.x, v1.y);
                A[mt][2] = packh2(v2.x, v2.y);
                A[mt][3] = packh2(v3.x, v3.y);
            }
#pragma unroll
            for (int np = 0; np < 2; np++)
                LDSM4(B[np], bBase + np * 16 * WPITCH + ks * 32);
#pragma unroll
            for (int mt = 0; mt < 2; mt++)
#pragma unroll
                for (int nt = 0; nt < 4; nt++)
                    MMA16816(acc[mt][nt], A[mt],
                             B[nt >> 1][(nt & 1) * 2], B[nt >> 1][(nt & 1) * 2 + 1]);
        }

        int row0 = tile * 128;
        float tmax = 0.f;
#pragma unroll
        for (int nt = 0; nt < 4; nt++) {
            int col = n_b + nt * 8 + 2 * t;
            float2 bb = *(float2*)(bsm + col);
#pragma unroll
            for (int mt = 0; mt < 2; mt++) {
                int rA = row0 + m_b + mt * 16 + g;
                int rB = rA + 8;
                float e0 = acc[mt][nt][0] + bb.x;
                float e1 = acc[mt][nt][1] + bb.y;
                float e2 = acc[mt][nt][2] + bb.x;
                float e3 = acc[mt][nt][3] + bb.y;
                tmax = fmaxf(tmax, fmaxf(fmaxf(fabsf(e0), fabsf(e1)),
                                         fmaxf(fabsf(e2), fabsf(e3))));
                if (rA < NROWS)
                    *(__half2*)(g_embh + (size_t)rA * D + col) = __floats2half2_rn(e0, e1);
                if (rB < NROWS)
                    *(__half2*)(g_embh + (size_t)rB * D + col) = __floats2half2_rn(e2, e3);
            }
        }
        unsigned um = __reduce_max_sync(0xffffffffu, __float_as_uint(tmax));
        if (lane == 0) atomicMax(&g_gmax_bits, um);

        __syncthreads();
        bufsel ^= 1;
    }
}

// ---------------------------------------------------------------------------
// Kernel 1b: int8 quantization with one GLOBAL scale (streaming convert).
// thread handles 8 halves; grid 6250 x 256 = 1.6M slots exact.
// ---------------------------------------------------------------------------
__global__ void __launch_bounds__(256) quant_kernel() {
    float gmax = __uint_as_float(g_gmax_bits);
    float inv  = 127.f / fmaxf(gmax, 1e-20f);

    size_t idx = (size_t)(blockIdx.x * 256 + threadIdx.x) * 8;
    uint4 v = *(const uint4*)(g_embh + idx);
    const __half2* h2 = (const __half2*)&v;
    int qi[8];
#pragma unroll
    for (int j = 0; j < 4; j++) {
        float2 f = __half22float2(h2[j]);
        qi[2 * j]     = max(-127, min(127, __float2int_rn(f.x * inv)));
        qi[2 * j + 1] = max(-127, min(127, __float2int_rn(f.y * inv)));
    }
    uint32_t p0 = (uint32_t)(qi[0] & 0xFF) | ((uint32_t)(qi[1] & 0xFF) << 8) |
                  ((uint32_t)(qi[2] & 0xFF) << 16) | ((uint32_t)(qi[3] & 0xFF) << 24);
    uint32_t p1 = (uint32_t)(qi[4] & 0xFF) | ((uint32_t)(qi[5] & 0xFF) << 8) |
                  ((uint32_t)(qi[6] & 0xFF) << 16) | ((uint32_t)(qi[7] & 0xFF) << 24);
    *(uint2*)(g_embi8 + idx) = make_uint2(p0, p1);
}

// ---------------------------------------------------------------------------
// Kernel 2: per (p, branch): logits, logsumexp, per-pair loss.
// Negatives: int8 rows, dp4a exact int32 dot + REDUX, single global scale^2.
// Positive dot from fp16 path.
// ---------------------------------------------------------------------------
__global__ void branch_kernel(const int* __restrict__ pos_anchor,
                              const int* __restrict__ pos_partner,
                              const int* __restrict__ neg_idx,
                              const int* __restrict__ weak_anchor,
                              const int* __restrict__ weak_partner,
                              const int* __restrict__ weak_neg_idx) {
    __shared__ float qsh[D], ksh[D];
    __shared__ int   sidx[NEG];
    __shared__ float sdots[NEG + 1];
    __shared__ uint32_t qi8[32];
    __shared__ float sred[9];

    int p  = blockIdx.x;
    int br = blockIdx.y;
    const int* anc = br ? weak_anchor  : pos_anchor;
    const int* par = br ? weak_partner : pos_partner;
    const int* nix = br ? weak_neg_idx : neg_idx;

    int tid  = threadIdx.x;
    int lane = tid & 31;
    int warp = tid >> 5;

    int a  = anc[p];
    int pr = par[p];
    if (tid < D) qsh[tid]     = __half2float(g_embh[(size_t)a  * D + tid]);
    else         ksh[tid - D] = __half2float(g_embh[(size_t)pr * D + (tid - D)]);
    sidx[tid] = nix[(size_t)p * NEG + tid];
    if (tid < 32) qi8[tid] = ((const uint32_t*)(g_embi8 + (size_t)a * D))[tid];
    __syncthreads();

    float gmax = __uint_as_float(g_gmax_bits);
    float gsc  = gmax * (1.f / 127.f);
    float gs2  = gsc * gsc;

    int grp = lane >> 3;            // 0..3: negative within quad
    int gl  = lane & 7;             // lane within 8-lane group
    uint32_t gmask = 0xFFu << (grp * 8);

    uint32_t qp[4];
#pragma unroll
    for (int j = 0; j < 4; j++) qp[j] = qi8[gl * 4 + j];

    // positive dot (warp 0, fp16-accuracy path)
    if (warp == 0) {
        float s = 0.f;
#pragma unroll
        for (int j = 0; j < 4; j++) s += qsh[lane * 4 + j] * ksh[lane * 4 + j];
#pragma unroll
        for (int m = 16; m >= 1; m >>= 1) s += __shfl_xor_sync(0xffffffffu, s, m);
        if (lane == 0) sdots[NEG] = s;
    }

    // negatives: 4 per warp-iteration, 8 lanes each (uint4 = 16 int8/lane)
#pragma unroll
    for (int it = 0; it < 8; it++) {
        int n  = warp * 32 + it * 4 + grp;
        int rw = sidx[n];
        uint4 v = *(const uint4*)(g_embi8 + (size_t)rw * D + gl * 16);
        int isum = 0;
        isum = __dp4a((int)v.x, (int)qp[0], isum);
        isum = __dp4a((int)v.y, (int)qp[1], isum);
        isum = __dp4a((int)v.z, (int)qp[2], isum);
        isum = __dp4a((int)v.w, (int)qp[3], isum);
        isum = __reduce_add_sync(gmask, isum);
        if (gl == 0) sdots[n] = (float)isum * gs2;
    }
    __syncthreads();

    const float invT = 1.0f / TEMPF;

    float v = sdots[tid];
    float mv = (tid == 0) ? fmaxf(v, sdots[NEG]) : v;
#pragma unroll
    for (int m = 16; m >= 1; m >>= 1) mv = fmaxf(mv, __shfl_xor_sync(0xffffffffu, mv, m));
    if (lane == 0) sred[warp] = mv;
    __syncthreads();
    if (tid == 0) {
        float m2 = sred[0];
#pragma unroll
        for (int i = 1; i < 8; i++) m2 = fmaxf(m2, sred[i]);
        sred[8] = m2;
    }
    __syncthreads();
    float ml = sred[8] * invT;

    float e = expf(v * invT - ml);
    if (tid == 0) e += expf(sdots[NEG] * invT - ml);
#pragma unroll
    for (int m = 16; m >= 1; m >>= 1) e += __shfl_xor_sync(0xffffffffu, e, m);
    if (lane == 0) sred[warp] = e;
    __syncthreads();
    if (tid == 0) {
        float s = 0.f;
#pragma unroll
        for (int i = 0; i < 8; i++) s += sred[i];
        g_losses[br * PP + p] = ml + logf(s) - sdots[NEG] * invT;
    }
}

// ---------------------------------------------------------------------------
// Kernel 3: deterministic mean reduction. 1024 threads, 8 independent loads
// per branch per thread (MLP-overlapped), then tree reduce.
// ---------------------------------------------------------------------------
__global__ void __launch_bounds__(1024) finalize_kernel(float* __restrict__ out) {
    __shared__ double s0sh[1024], s1sh[1024];
    int tid = threadIdx.x;
    double s0 = 0.0, s1 = 0.0;
#pragma unroll
    for (int i = 0; i < PP / 1024; i++) {
        s0 += (double)g_losses[i * 1024 + tid];
        s1 += (double)g_losses[PP + i * 1024 + tid];
    }
    s0sh[tid] = s0; s1sh[tid] = s1;
    __syncthreads();
    for (int st = 512; st > 0; st >>= 1) {
        if (tid < st) { s0sh[tid] += s0sh[tid + st]; s1sh[tid] += s1sh[tid + st]; }
        __syncthreads();
    }
    if (tid == 0)
        out[0] = (float)(s0sh[0] / (double)PP + 0.1 * (s1sh[0] / (double)PP));
}

extern "C" void kernel_launch(void* const* d_in, const int* in_sizes, int n_in,
                              void* d_out, int out_size) {
    const float* X  = (const float*)d_in[0];
    const float* W  = (const float*)d_in[1];
    const float* b  = (const float*)d_in[2];
    const int*   pa = (const int*)d_in[3];
    const int*   pp = (const int*)d_in[4];
    const int*   ni = (const int*)d_in[5];
    const int*   wa = (const int*)d_in[6];
    const int*   wp = (const int*)d_in[7];
    const int*   wn = (const int*)d_in[8];
    float* out = (float*)d_out;

    cudaFuncSetAttribute(gemm_kernel, cudaFuncAttributeMaxDynamicSharedMemorySize, GEMM_SMEM);

    init_kernel<<<1, 1>>>();
    gemm_kernel<<<148, 512, GEMM_SMEM>>>(X, W, b);
    quant_kernel<<<(NROWS * D / 8) / 256, 256>>>();   // 6250 blocks exact
    branch_kernel<<<dim3(PP, 2), 256>>>(pa, pp, ni, wa, wp, wn);
    finalize_kernel<<<1, 1024>>>(out);
}